// round 6
// baseline (speedup 1.0000x reference)
#include <cuda_runtime.h>
#include <math.h>

#define N_POINTS 128
#define STEPS    50
#define N_EVENTS 10000
#define DT       2.0f
#define SQRT_PI_F 1.7724539f

#define N_PAIRS    ((N_POINTS * (N_POINTS - 1)) / 2)      // 8128
#define PAIR_TOTAL (N_PAIRS * STEPS)                      // 406400
#define TOTAL_WORK (PAIR_TOTAL + N_EVENTS)                // 416400

#define BLOCKS  592
#define THREADS 256
#define CHUNK   3                                         // 592*256*3 >= TOTAL_WORK

// ---- device scratch (allocation-free contract) ----
__device__ float g_Z[2 * N_POINTS * STEPS];               // [row = point*2+dim][s]
__device__ float g_ts[STEPS + 1];                         // ts[s]; slot 50 = times[M-1]
__device__ float g_vl[STEPS];                             // valid mask (0/1)
__device__ unsigned int g_ticket = 0;
__device__ unsigned int g_flag   = 0;
__device__ unsigned int g_count  = 0;
__device__ double       g_acc    = 0.0;

__device__ __forceinline__ int tri_base(int i) {          // # pairs before row i
    return i * (N_POINTS - 1) - (i * (i - 1)) / 2;
}

// Abramowitz-Stegun 7.1.26: |err| < 1.5e-7
__device__ __forceinline__ float fast_erff(float x) {
    float ax = fabsf(x);
    float t  = __fdividef(1.0f, fmaf(0.3275911f, ax, 1.0f));
    float poly = t * fmaf(t, fmaf(t, fmaf(t, fmaf(t, 1.061405429f,
                    -1.453152027f), 1.421413741f), -0.284496736f), 0.254829592f);
    float r = 1.0f - poly * __expf(-ax * ax);
    return copysignf(r, x);
}

__global__ void __launch_bounds__(THREADS)
fused_kernel(const float* __restrict__ data,
             const float* __restrict__ beta,
             const float* __restrict__ z0,
             const float* __restrict__ v0,
             float* __restrict__ out) {
    const int   tid   = threadIdx.x;
    const float denom = DT + DT * 0.001f;                 // 2.002f, matches ref rounding
    const float b0    = __ldg(&beta[0]);

    __shared__ unsigned int s_role;
    __shared__ double sRd[THREADS / 32];

    if (tid == 0) s_role = atomicAdd(&g_ticket, 1u);
    __syncthreads();

    if (s_role == 0) {
        // ================= producer block: compute tables ONCE =================
        float tlast = __ldg(&data[(N_EVENTS - 1) * 3 + 2]);
        if (tid <= STEPS) {
            g_ts[tid] = tlast;                            // empty segment -> times[M-1]
            if (tid < STEPS) g_vl[tid] = 0.0f;
        }
        // Z cumsum: one row per thread (exactly 256 rows)
        {
            float z = __ldg(&z0[tid]);
            const float* vr = v0 + tid * STEPS;
            float* Zr = g_Z + tid * STEPS;
            Zr[0] = z;                                    // Z_steps[0] = z0
            float cum = 0.0f;
            #pragma unroll
            for (int s = 1; s < STEPS; ++s) {
                cum += z + vr[s - 1] * DT;                // Z_steps[s]
                Zr[s] = cum;
            }
        }
        __syncthreads();                                  // defaults before scan overwrite
        // boundary scan over sorted event times (independent loads, MLP-hidden)
        for (int m = tid; m < N_EVENTS; m += THREADS) {
            float t   = data[m * 3 + 2];
            int   idx = (int)floorf(t / denom);
            int newseg = (m == 0) ||
                         (((int)floorf(data[m * 3 - 1] / denom)) != idx);
            if (newseg) { g_ts[idx] = t; g_vl[idx] = 1.0f; }
        }
        __syncthreads();
        if (tid == 0) {
            __threadfence();                              // release tables
            atomicExch(&g_flag, 1u);
        }
        __syncthreads();
    } else {
        // ================= consumer blocks: wait for tables =================
        if (tid == 0) {
            while (atomicAdd(&g_flag, 0u) == 0u) __nanosleep(32);
            __threadfence();                              // acquire
        }
        __syncthreads();
    }

    // ---- main phase: contiguous chunk of terms per thread ----
    double local = 0.0;
    int t0 = (blockIdx.x * THREADS + tid) * CHUNK;
    if (t0 < TOTAL_WORK) {
        int i = 0, j = 1, s = 0;
        if (t0 < PAIR_TOTAL) {                            // triangular decode + fixup
            int p = t0 / STEPS;
            s = t0 - p * STEPS;
            float disc = (float)(255 * 255 - 8 * p);
            i = (int)((255.0f - sqrtf(disc)) * 0.5f);
            i = min(max(i, 0), N_POINTS - 2);
            while (i < N_POINTS - 2 && tri_base(i + 1) <= p) ++i;
            while (i > 0 && tri_base(i) > p) --i;
            j = i + 1 + (p - tri_base(i));
        }

        #pragma unroll
        for (int k = 0; k < CHUNK; ++k) {
            int q = t0 + k;
            if (q >= TOTAL_WORK) break;
            if (q < PAIR_TOTAL) {
                int oi = i * 100 + s, oj = j * 100 + s;
                float dzx = __ldg(&g_Z[oi])      - __ldg(&g_Z[oj]);
                float dzy = __ldg(&g_Z[oi + 50]) - __ldg(&g_Z[oj + 50]);
                float dvx = __ldg(&v0[oi])       - __ldg(&v0[oj]);
                float dvy = __ldg(&v0[oi + 50])  - __ldg(&v0[oj + 50]);

                float a = fmaxf(dvx * dvx + dvy * dvy, 1e-10f);
                float b = 2.0f * (dzx * dvx + dzy * dvy);
                float c = dzx * dzx + dzy * dzy;
                float rsa    = rsqrtf(a);
                float inv2sa = 0.5f * rsa;
                float shift  = b * inv2sa;
                float arg    = b0 - c + shift * shift;
                if (arg > -25.0f) {                       // exp-underflow skip
                    float sa  = a * rsa;
                    float ts  = __ldg(&g_ts[s]);
                    float tf  = __ldg(&g_ts[s + 1]);
                    float loa = fmaf(sa, ts, shift);
                    float hia = fmaf(sa, tf, shift);
                    if (loa < 5.0f && hia > -5.0f) {      // erf-saturation skip
                        float pref  = SQRT_PI_F * inv2sa * __expf(arg);
                        float integ = pref * (fast_erff(hia) - fast_erff(loa));
                        local -= (double)(integ * __ldg(&g_vl[s]));
                    }
                }
                if (++s == STEPS) {                       // advance (i,j,s)
                    s = 0;
                    if (++j == N_POINTS) { ++i; j = i + 1; }
                }
            } else {
                int e = q - PAIR_TOTAL;
                float si = data[e * 3], dj = data[e * 3 + 1], t = data[e * 3 + 2];
                int ii = (int)si, jj = (int)dj;
                float stepf = floorf(t / denom);
                int   id    = (int)stepf;
                float delta = t - stepf * DT;
                int oi = ii * 100 + id, oj = jj * 100 + id;
                float dx = (__ldg(&g_Z[oi])      + __ldg(&v0[oi])      * delta)
                         - (__ldg(&g_Z[oj])      + __ldg(&v0[oj])      * delta);
                float dy = (__ldg(&g_Z[oi + 50]) + __ldg(&v0[oi + 50]) * delta)
                         - (__ldg(&g_Z[oj + 50]) + __ldg(&v0[oj + 50]) * delta);
                local += (double)(b0 - (dx * dx + dy * dy));
            }
        }
    }

    // ---- reduction: warp shuffle -> smem -> warp0 -> global atomic ----
    double v = local;
    #pragma unroll
    for (int off = 16; off > 0; off >>= 1)
        v += __shfl_down_sync(0xffffffffu, v, off);
    int warp = tid >> 5, lane = tid & 31;
    if (lane == 0) sRd[warp] = v;
    __syncthreads();
    if (warp == 0) {
        v = (lane < THREADS / 32) ? sRd[lane] : 0.0;
        #pragma unroll
        for (int off = 4; off > 0; off >>= 1)
            v += __shfl_down_sync(0xffffffffu, v, off);
        if (lane == 0) {
            atomicAdd(&g_acc, v);
            __threadfence();
            unsigned int old = atomicAdd(&g_count, 1u);
            if (old == gridDim.x - 1) {                   // last block: write + reset
                double total = atomicAdd(&g_acc, 0.0);
                out[0] = (float)total;
                g_acc    = 0.0;
                g_count  = 0u;
                g_flag   = 0u;
                g_ticket = 0u;
            }
        }
    }
}

// Inputs (metadata order): data[30000], t0[1], tn[1], beta[1], z0[256], v0[12800]
extern "C" void kernel_launch(void* const* d_in, const int* in_sizes, int n_in,
                              void* d_out, int out_size) {
    const float* data = (const float*)d_in[0];
    const float* beta = (const float*)d_in[3];
    const float* z0   = (const float*)d_in[4];
    const float* v0   = (const float*)d_in[5];
    float* out = (float*)d_out;

    fused_kernel<<<BLOCKS, THREADS>>>(data, beta, z0, v0, out);
}